// round 3
// baseline (speedup 1.0000x reference)
#include <cuda_runtime.h>

#define NTHREADS 384
#define DIM_NX 64
#define DIM_NQ 64
#define DIM_NU 16
#define XS_STRIDE 65   // odd stride -> conflict-free per-lane scalar access
#define US_STRIDE 17

// SMEM float counts:
// C1T 4096 | D12T 1024 | D11 4096 | AT 4096 | B1T 4096 | B2T 1024 | bv 64 | bx 64
// xs 384*65 | us 384*17        (no ws: xs row is reused for w after x dies)
#define MAT_FLOATS  (4096*4 + 1024*2 + 128)
#define SMEM_FLOATS (MAT_FLOATS + NTHREADS*XS_STRIDE + NTHREADS*US_STRIDE)

__global__ void __launch_bounds__(NTHREADS, 1)
renl2_kernel(const float* __restrict__ gx,  const float* __restrict__ gu,
             const float* __restrict__ gA,  const float* __restrict__ gB1,
             const float* __restrict__ gB2, const float* __restrict__ gC1,
             const float* __restrict__ gD11,const float* __restrict__ gD12,
             const float* __restrict__ gbv, const float* __restrict__ gbx,
             float* __restrict__ gout, int N)
{
    extern __shared__ float sm[];
    float* sC1T  = sm;                 // [j][i] = C1[i][j]
    float* sD12T = sC1T  + 4096;       // [k][i] = D12[i][k]
    float* sD11  = sD12T + 1024;       // row-major (rows 16B aligned)
    float* sAT   = sD11  + 4096;       // [j][k] = A[k][j]
    float* sB1T  = sAT   + 4096;       // [j][k] = B1[k][j]
    float* sB2T  = sB1T  + 4096;       // [j][k] = B2[k][j]
    float* sbv   = sB2T  + 1024;
    float* sbx   = sbv   + 64;
    float* xs    = sbx   + 64;                       // [384][65]
    float* us    = xs    + NTHREADS * XS_STRIDE;     // [384][17]

    const int tid     = threadIdx.x;
    const int rowbase = blockIdx.x * NTHREADS;

    // ---- stage matrices (transpose on the fly; one-time)
    for (int idx = tid; idx < 4096; idx += NTHREADS) {
        const int i = idx >> 6, j = idx & 63;
        sC1T[j * 64 + i] = gC1[idx];
        sD11[idx]        = gD11[idx];
        sAT [j * 64 + i] = gA [idx];
        sB1T[j * 64 + i] = gB1[idx];
    }
    for (int idx = tid; idx < 1024; idx += NTHREADS) {
        const int i = idx >> 4, k = idx & 15;
        sD12T[k * 64 + i] = gD12[idx];
        sB2T [k * 64 + i] = gB2 [idx];
    }
    if (tid < 64) { sbv[tid] = gbv[tid]; sbx[tid] = gbx[tid]; }

    // ---- stage x, u tiles (coalesced float4 global reads; guard tail CTA)
    const float4* gx4 = reinterpret_cast<const float4*>(gx + (size_t)rowbase * DIM_NX);
    #pragma unroll 1
    for (int idx4 = tid; idx4 < NTHREADS * DIM_NX / 4; idx4 += NTHREADS) {
        const int r = idx4 >> 4, c = (idx4 & 15) << 2;
        if (rowbase + r < N) {
            const float4 v = gx4[idx4];
            float* p = &xs[r * XS_STRIDE + c];
            p[0] = v.x; p[1] = v.y; p[2] = v.z; p[3] = v.w;
        }
    }
    const float4* gu4 = reinterpret_cast<const float4*>(gu + (size_t)rowbase * DIM_NU);
    #pragma unroll 1
    for (int idx4 = tid; idx4 < NTHREADS * DIM_NU / 4; idx4 += NTHREADS) {
        const int r = idx4 >> 2, c = (idx4 & 3) << 2;
        if (rowbase + r < N) {
            const float4 v = gu4[idx4];
            float* p = &us[r * US_STRIDE + c];
            p[0] = v.x; p[1] = v.y; p[2] = v.z; p[3] = v.w;
        }
    }
    __syncthreads();

    const float* myx = &xs[tid * XS_STRIDE];
    const float* myu = &us[tid * US_STRIDE];

    // ================= phase A: fused base + x/u epilogue contributions
    //   w[i]   = bv[i] + C1[i,:]x + D12[i,:]u
    //   out[k] = bx[k] + A[k,:]x  + B2[k,:]u
    float w[DIM_NQ], out[DIM_NX];
    #pragma unroll
    for (int i = 0; i < DIM_NQ; i++) w[i] = sbv[i];
    #pragma unroll
    for (int k = 0; k < DIM_NX; k++) out[k] = sbx[k];

    #pragma unroll 2
    for (int j = 0; j < DIM_NX; j++) {
        const float xj = myx[j];
        const float4* crow = reinterpret_cast<const float4*>(&sC1T[j * 64]);
        const float4* arow = reinterpret_cast<const float4*>(&sAT [j * 64]);
        #pragma unroll
        for (int q = 0; q < 16; q++) {
            const float4 c = crow[q];
            w[4*q+0] = fmaf(c.x, xj, w[4*q+0]);
            w[4*q+1] = fmaf(c.y, xj, w[4*q+1]);
            w[4*q+2] = fmaf(c.z, xj, w[4*q+2]);
            w[4*q+3] = fmaf(c.w, xj, w[4*q+3]);
            const float4 a = arow[q];
            out[4*q+0] = fmaf(a.x, xj, out[4*q+0]);
            out[4*q+1] = fmaf(a.y, xj, out[4*q+1]);
            out[4*q+2] = fmaf(a.z, xj, out[4*q+2]);
            out[4*q+3] = fmaf(a.w, xj, out[4*q+3]);
        }
    }
    #pragma unroll 1
    for (int k = 0; k < DIM_NU; k++) {
        const float uk = myu[k];
        const float4* drow = reinterpret_cast<const float4*>(&sD12T[k * 64]);
        const float4* brow = reinterpret_cast<const float4*>(&sB2T [k * 64]);
        #pragma unroll
        for (int q = 0; q < 16; q++) {
            const float4 d = drow[q];
            w[4*q+0] = fmaf(d.x, uk, w[4*q+0]);
            w[4*q+1] = fmaf(d.y, uk, w[4*q+1]);
            w[4*q+2] = fmaf(d.z, uk, w[4*q+2]);
            w[4*q+3] = fmaf(d.w, uk, w[4*q+3]);
            const float4 b = brow[q];
            out[4*q+0] = fmaf(b.x, uk, out[4*q+0]);
            out[4*q+1] = fmaf(b.y, uk, out[4*q+1]);
            out[4*q+2] = fmaf(b.z, uk, out[4*q+2]);
            out[4*q+3] = fmaf(b.w, uk, out[4*q+3]);
        }
    }

    // ================= phase B: forward substitution with ReLU
    // D11 strictly lower triangular: float4 groups, padded lanes multiply by 0.
    w[0] = fmaxf(w[0], 0.0f);
    #pragma unroll
    for (int i = 1; i < DIM_NQ; i++) {
        const float4* drow = reinterpret_cast<const float4*>(&sD11[i * 64]);
        float a0 = w[i], a1 = 0.0f, a2 = 0.0f, a3 = 0.0f;
        const int ng = (i >> 2) + 1;
        #pragma unroll
        for (int g = 0; g < 16; g++) {
            if (g >= ng) break;                  // compile-time trimmed per i
            const float4 d = drow[g];
            a0 = fmaf(d.x, w[4*g+0], a0);
            a1 = fmaf(d.y, w[4*g+1], a1);
            a2 = fmaf(d.z, w[4*g+2], a2);
            a3 = fmaf(d.w, w[4*g+3], a3);
        }
        w[i] = fmaxf((a0 + a1) + (a2 + a3), 0.0f);
    }

    // x is dead now: reuse this thread's PRIVATE xs row for w (no sync needed —
    // no other thread touches this row between here and the final barrier).
    float* myw = &xs[tid * XS_STRIDE];
    #pragma unroll
    for (int i = 0; i < DIM_NQ; i++) myw[i] = w[i];

    // ================= phase C: out += B1 w
    #pragma unroll 2
    for (int i = 0; i < DIM_NQ; i++) {
        const float wi = myw[i];
        const float4* brow = reinterpret_cast<const float4*>(&sB1T[i * 64]);
        #pragma unroll
        for (int q = 0; q < 16; q++) {
            const float4 b = brow[q];
            out[4*q+0] = fmaf(b.x, wi, out[4*q+0]);
            out[4*q+1] = fmaf(b.y, wi, out[4*q+1]);
            out[4*q+2] = fmaf(b.z, wi, out[4*q+2]);
            out[4*q+3] = fmaf(b.w, wi, out[4*q+3]);
        }
    }

    // ---- stage result through own xs row, then fully coalesced stores
    #pragma unroll
    for (int k = 0; k < DIM_NX; k++) myw[k] = out[k];   // private row, safe
    __syncthreads();                                    // before cross-row reads

    float4* gout4 = reinterpret_cast<float4*>(gout + (size_t)rowbase * DIM_NX);
    #pragma unroll 1
    for (int idx4 = tid; idx4 < NTHREADS * DIM_NX / 4; idx4 += NTHREADS) {
        const int r = idx4 >> 4, c = (idx4 & 15) << 2;
        if (rowbase + r < N) {
            const float* p = &xs[r * XS_STRIDE + c];
            gout4[idx4] = make_float4(p[0], p[1], p[2], p[3]);
        }
    }
}

extern "C" void kernel_launch(void* const* d_in, const int* in_sizes, int n_in,
                              void* d_out, int out_size) {
    (void)n_in; (void)out_size;
    const float* x   = (const float*)d_in[0];
    const float* u   = (const float*)d_in[1];
    const float* A   = (const float*)d_in[2];
    const float* B1  = (const float*)d_in[3];
    const float* B2  = (const float*)d_in[4];
    const float* C1  = (const float*)d_in[5];
    const float* D11 = (const float*)d_in[6];
    const float* D12 = (const float*)d_in[7];
    const float* bv  = (const float*)d_in[8];
    const float* bx  = (const float*)d_in[9];
    float* out = (float*)d_out;

    const int N = in_sizes[0] / DIM_NX;          // 262144
    const int grid = (N + NTHREADS - 1) / NTHREADS;
    const size_t smem_bytes = (size_t)SMEM_FLOATS * sizeof(float);  // ~195.5 KB

    cudaFuncSetAttribute(renl2_kernel,
                         cudaFuncAttributeMaxDynamicSharedMemorySize,
                         (int)smem_bytes);

    renl2_kernel<<<grid, NTHREADS, smem_bytes>>>(
        x, u, A, B1, B2, C1, D11, D12, bv, bx, out, N);
}

// round 4
// speedup vs baseline: 1.1286x; 1.1286x over previous
#include <cuda_runtime.h>

#define NTHREADS 256
#define NWARPS   8
#define R        16            // rows per warp
#define ROWS_CTA (NWARPS * R)  // 128
#define DIM_NX 64
#define DIM_NQ 64
#define DIM_NU 16

// smem floats: C1p 4096 | Ap 4096 | B1p 4096 | D11p 4096 | D12p 1024 | B2p 1024
//              xs 128*64 | us 128*16   => 28672 floats = 112 KB
#define SMEM_FLOATS (4096*4 + 1024*2 + ROWS_CTA*DIM_NX + ROWS_CTA*DIM_NU)

typedef unsigned long long u64t;

__device__ __forceinline__ u64t pk2(float a, float b) {
    u64t r; asm("mov.b64 %0, {%1, %2};" : "=l"(r) : "f"(a), "f"(b)); return r;
}
__device__ __forceinline__ void up2(u64t v, float& a, float& b) {
    asm("mov.b64 {%0, %1}, %2;" : "=f"(a), "=f"(b) : "l"(v));
}
__device__ __forceinline__ u64t fma2(u64t a, u64t b, u64t c) {
    u64t d; asm("fma.rn.f32x2 %0, %1, %2, %3;" : "=l"(d) : "l"(a), "l"(b), "l"(c));
    return d;
}

__global__ void __launch_bounds__(NTHREADS)
renl2_kernel(const float* __restrict__ gx,  const float* __restrict__ gu,
             const float* __restrict__ gA,  const float* __restrict__ gB1,
             const float* __restrict__ gB2, const float* __restrict__ gC1,
             const float* __restrict__ gD11,const float* __restrict__ gD12,
             const float* __restrict__ gbv, const float* __restrict__ gbx,
             float* __restrict__ gout, int N)
{
    extern __shared__ float sm[];
    float* sC1p  = sm;                  // [j][lane] -> {C1[l][j],  C1[l+32][j]}
    float* sAp   = sC1p  + 4096;        // [j][lane] -> {A[l][j],   A[l+32][j]}
    float* sB1p  = sAp   + 4096;        // [i][lane] -> {B1[l][i],  B1[l+32][i]}
    float* sD11p = sB1p  + 4096;        // [j][lane] -> {D11[l][j], D11[l+32][j]}
    float* sD12p = sD11p + 4096;        // [k][lane] -> {D12[l][k], D12[l+32][k]}
    float* sB2p  = sD12p + 1024;        // [k][lane] -> {B2[l][k],  B2[l+32][k]}
    float* xs    = sB2p  + 1024;        // [128][64]
    float* us    = xs + ROWS_CTA*DIM_NX;// [128][16]

    const int tid     = threadIdx.x;
    const int lane    = tid & 31;
    const int wid     = tid >> 5;
    const int rowbase = blockIdx.x * ROWS_CTA;

    // ---- stage matrices as lane-packed float2 (one-time per CTA)
    float2* C1p2  = reinterpret_cast<float2*>(sC1p);
    float2* Ap2   = reinterpret_cast<float2*>(sAp);
    float2* B1p2  = reinterpret_cast<float2*>(sB1p);
    float2* D11p2 = reinterpret_cast<float2*>(sD11p);
    float2* D12p2 = reinterpret_cast<float2*>(sD12p);
    float2* B2p2  = reinterpret_cast<float2*>(sB2p);

    #pragma unroll 1
    for (int idx = tid; idx < 2048; idx += NTHREADS) {
        const int j = idx >> 5, l = idx & 31;
        C1p2 [idx] = make_float2(gC1 [l*64 + j], gC1 [(l+32)*64 + j]);
        Ap2  [idx] = make_float2(gA  [l*64 + j], gA  [(l+32)*64 + j]);
        B1p2 [idx] = make_float2(gB1 [l*64 + j], gB1 [(l+32)*64 + j]);
        D11p2[idx] = make_float2(gD11[l*64 + j], gD11[(l+32)*64 + j]);
    }
    #pragma unroll 1
    for (int idx = tid; idx < 512; idx += NTHREADS) {
        const int k = idx >> 5, l = idx & 31;
        D12p2[idx] = make_float2(gD12[l*16 + k], gD12[(l+32)*16 + k]);
        B2p2 [idx] = make_float2(gB2 [l*16 + k], gB2 [(l+32)*16 + k]);
    }

    // ---- stage x, u tiles: contiguous copy (fully coalesced float4)
    const float4* gx4 = reinterpret_cast<const float4*>(gx + (size_t)rowbase * DIM_NX);
    float4* xs4 = reinterpret_cast<float4*>(xs);
    #pragma unroll 1
    for (int i = tid; i < ROWS_CTA * DIM_NX / 4; i += NTHREADS) {
        if (rowbase + (i >> 4) < N) xs4[i] = gx4[i];
    }
    const float4* gu4 = reinterpret_cast<const float4*>(gu + (size_t)rowbase * DIM_NU);
    float4* us4 = reinterpret_cast<float4*>(us);
    #pragma unroll 1
    for (int i = tid; i < ROWS_CTA * DIM_NU / 4; i += NTHREADS) {
        if (rowbase + (i >> 2) < N) us4[i] = gu4[i];
    }
    __syncthreads();

    const u64t* uC1  = reinterpret_cast<const u64t*>(sC1p);
    const u64t* uA   = reinterpret_cast<const u64t*>(sAp);
    const u64t* uB1  = reinterpret_cast<const u64t*>(sB1p);
    const u64t* uD11 = reinterpret_cast<const u64t*>(sD11p);
    const u64t* uD12 = reinterpret_cast<const u64t*>(sD12p);
    const u64t* uB2  = reinterpret_cast<const u64t*>(sB2p);

    const float* myxs = xs + (wid * R) * DIM_NX;
    const float* myus = us + (wid * R) * DIM_NU;

    // accumulators: lane l holds (v[l], v[l+32]) packed, per row
    const float bvlo = gbv[lane], bvhi = gbv[lane + 32];
    const float bxlo = gbx[lane], bxhi = gbx[lane + 32];
    u64t wac[R], opk[R];
    #pragma unroll
    for (int r = 0; r < R; r++) { wac[r] = pk2(bvlo, bvhi); opk[r] = pk2(bxlo, bxhi); }

    // ===== phase A: w += C1 x ; out += A x   (matrix LDS amortized over R rows)
    #pragma unroll 2
    for (int j = 0; j < DIM_NX; j++) {
        const u64t c1 = uC1[j * 32 + lane];
        const u64t aa = uA [j * 32 + lane];
        #pragma unroll
        for (int r = 0; r < R; r++) {
            const float xj = myxs[r * DIM_NX + j];   // broadcast, 1 wavefront
            const u64t x2 = pk2(xj, xj);
            wac[r] = fma2(c1, x2, wac[r]);
            opk[r] = fma2(aa, x2, opk[r]);
        }
    }
    // ===== phase A-u: w += D12 u ; out += B2 u
    #pragma unroll 1
    for (int k = 0; k < DIM_NU; k++) {
        const u64t dd = uD12[k * 32 + lane];
        const u64t bb = uB2 [k * 32 + lane];
        #pragma unroll
        for (int r = 0; r < R; r++) {
            const float uk = myus[r * DIM_NU + k];
            const u64t u2 = pk2(uk, uk);
            wac[r] = fma2(dd, u2, wac[r]);
            opk[r] = fma2(bb, u2, opk[r]);
        }
    }

    // ===== fused substitution + epilogue:
    //   step j: w_j = relu(acc at lane j), then acc += D11[:,j]*w_j, out += B1[:,j]*w_j
    //   D11 strictly lower => lanes with index <= j add exactly 0 (zeros stored).
    #pragma unroll 2
    for (int j = 0; j < 32; j++) {                    // w indices 0..31 (lo half)
        const u64t dj = uD11[j * 32 + lane];
        const u64t bj = uB1 [j * 32 + lane];
        #pragma unroll
        for (int r = 0; r < R; r++) {
            float alo, ahi; up2(wac[r], alo, ahi);
            const float wj = fmaxf(__shfl_sync(0xffffffffu, alo, j), 0.0f);
            const u64t w2 = pk2(wj, wj);
            wac[r] = fma2(dj, w2, wac[r]);
            opk[r] = fma2(bj, w2, opk[r]);
        }
    }
    #pragma unroll 2
    for (int j = 32; j < 64; j++) {                   // w indices 32..63 (hi half)
        const u64t dj = uD11[j * 32 + lane];
        const u64t bj = uB1 [j * 32 + lane];
        #pragma unroll
        for (int r = 0; r < R; r++) {
            float alo, ahi; up2(wac[r], alo, ahi);
            const float wj = fmaxf(__shfl_sync(0xffffffffu, ahi, j - 32), 0.0f);
            const u64t w2 = pk2(wj, wj);
            wac[r] = fma2(dj, w2, wac[r]);
            opk[r] = fma2(bj, w2, opk[r]);
        }
    }

    // ===== store: row-major, lane l writes cols l and l+32 (coalesced 128B halves)
    #pragma unroll
    for (int r = 0; r < R; r++) {
        const int row = rowbase + wid * R + r;
        if (row < N) {
            float olo, ohi; up2(opk[r], olo, ohi);
            gout[(size_t)row * DIM_NX + lane]      = olo;
            gout[(size_t)row * DIM_NX + lane + 32] = ohi;
        }
    }
}

extern "C" void kernel_launch(void* const* d_in, const int* in_sizes, int n_in,
                              void* d_out, int out_size) {
    (void)n_in; (void)out_size;
    const float* x   = (const float*)d_in[0];
    const float* u   = (const float*)d_in[1];
    const float* A   = (const float*)d_in[2];
    const float* B1  = (const float*)d_in[3];
    const float* B2  = (const float*)d_in[4];
    const float* C1  = (const float*)d_in[5];
    const float* D11 = (const float*)d_in[6];
    const float* D12 = (const float*)d_in[7];
    const float* bv  = (const float*)d_in[8];
    const float* bx  = (const float*)d_in[9];
    float* out = (float*)d_out;

    const int N = in_sizes[0] / DIM_NX;                 // 262144
    const int grid = (N + ROWS_CTA - 1) / ROWS_CTA;     // 2048
    const size_t smem_bytes = (size_t)SMEM_FLOATS * sizeof(float);  // 112 KB

    cudaFuncSetAttribute(renl2_kernel,
                         cudaFuncAttributeMaxDynamicSharedMemorySize,
                         (int)smem_bytes);

    renl2_kernel<<<grid, NTHREADS, smem_bytes>>>(
        x, u, A, B1, B2, C1, D11, D12, bv, bx, out, N);
}